// round 1
// baseline (speedup 1.0000x reference)
#include <cuda_runtime.h>
#include <math.h>

// ---------------- problem constants ----------------
#define NIMG   1536            // B*S = 32*48
#define UNITS  48
#define SENS   1283
#define NB     32
#define NS     48

// conv geometry
#define H0 48
#define W0 72
#define H1 23
#define W1 35
#define H2 11
#define W2 17
#define H3 5
#define W3 8

#define C0OUT (32*H1*W1)       // 25760
#define C1OUT (64*H2*W2)       // 11968

// ---------------- scratch (device globals; no mallocs allowed) ----------------
__device__ float  g_c0[(size_t)NIMG * C0OUT];       // conv0 output  (~158MB)
__device__ float  g_c1[(size_t)NIMG * C1OUT];       // conv1 output  (~73MB)
__device__ float  g_x [(size_t)NIMG * SENS];        // sensory input x (feat+relpos)
__device__ float  g_sn[(size_t)NIMG * UNITS];       // sensory numerator sums
__device__ float  g_sd[(size_t)NIMG * UNITS];       // sensory denominator sums
__device__ float4 g_sp[SENS * UNITS];               // fused sensory synapse params
__device__ float4 g_rp[UNITS * UNITS];              // fused recurrent synapse params

// ---------------- fast math helpers ----------------
__device__ __forceinline__ float ex2f(float x) {
    float y; asm("ex2.approx.f32 %0, %1;" : "=f"(y) : "f"(x)); return y;
}
__device__ __forceinline__ float rcpf(float x) {
    float y; asm("rcp.approx.f32 %0, %1;" : "=f"(y) : "f"(x)); return y;
}
// sigmoid(z) with z pre-transformed: stored params give nz = x*A + C where
// nz = -z*log2(e);  sigmoid = 1/(1+2^nz)

// ---------------- prep: fold affine, log2e, mask, erev into params ----------------
__global__ void k_prep_sens(const float* __restrict__ iw, const float* __restrict__ ib,
                            const float* __restrict__ ssig, const float* __restrict__ smu,
                            const float* __restrict__ sw, const float* __restrict__ serev,
                            const int* __restrict__ smask) {
    int idx = blockIdx.x * blockDim.x + threadIdx.x;
    if (idx >= SENS * UNITS) return;
    int k = idx / UNITS;
    const float L = 1.4426950408889634f;
    float sg = ssig[idx], m = smu[idx];
    float w  = sw[idx] * (float)smask[idx];
    // z = ((x*iw+ib) - m)*sg ;  nz = -L*z = x*(-L*sg*iw) + L*sg*(m - ib)
    float A = -L * sg * iw[k];
    float C =  L * sg * (m - ib[k]);
    g_sp[idx] = make_float4(A, C, w * serev[idx], w);
}

__global__ void k_prep_rec(const float* __restrict__ sigma, const float* __restrict__ mu,
                           const float* __restrict__ wsyn, const float* __restrict__ erev,
                           const int* __restrict__ mask) {
    int idx = blockIdx.x * blockDim.x + threadIdx.x;
    if (idx >= UNITS * UNITS) return;
    const float L = 1.4426950408889634f;
    float sg = sigma[idx], m = mu[idx];
    float w  = wsyn[idx] * (float)mask[idx];
    float A = -L * sg;
    float C =  L * sg * m;
    g_rp[idx] = make_float4(A, C, w * erev[idx], w);
}

// ---------------- conv0: 1->32, 48x72 -> 23x35 ----------------
__global__ void __launch_bounds__(256) k_conv0(const float* __restrict__ image,
                                               const float* __restrict__ w0,
                                               const float* __restrict__ b0) {
    __shared__ float simg[H0 * W0];   // 3456
    __shared__ float sw[32 * 9];
    int img = blockIdx.x, tid = threadIdx.x;
    const float* src = image + (size_t)img * (H0 * W0);
    for (int i = tid; i < H0 * W0; i += 256) simg[i] = src[i];
    for (int i = tid; i < 288; i += 256) sw[i] = w0[i];
    __syncthreads();
    // tasks: 16 oc-pairs * 23 oy * 5 ox-groups(7 wide) = 1840
    for (int task = tid; task < 1840; task += 256) {
        int oc0 = (task / 115) * 2;
        int rem = task % 115;
        int oy = rem / 5;
        int ox0 = (rem % 5) * 7;
        float wr0[9], wr1[9];
        #pragma unroll
        for (int j = 0; j < 9; j++) { wr0[j] = sw[oc0 * 9 + j]; wr1[j] = sw[(oc0 + 1) * 9 + j]; }
        float a0[7], a1[7];
        float bb0 = b0[oc0], bb1 = b0[oc0 + 1];
        #pragma unroll
        for (int o = 0; o < 7; o++) { a0[o] = bb0; a1[o] = bb1; }
        #pragma unroll
        for (int ky = 0; ky < 3; ky++) {
            const float* row = &simg[(2 * oy + ky) * W0 + 2 * ox0];
            float r[15];
            #pragma unroll
            for (int j = 0; j < 15; j++) r[j] = row[j];
            #pragma unroll
            for (int kx = 0; kx < 3; kx++) {
                float wa = wr0[ky * 3 + kx], wb = wr1[ky * 3 + kx];
                #pragma unroll
                for (int o = 0; o < 7; o++) {
                    a0[o] = fmaf(wa, r[2 * o + kx], a0[o]);
                    a1[o] = fmaf(wb, r[2 * o + kx], a1[o]);
                }
            }
        }
        float* out0 = &g_c0[(size_t)img * C0OUT + oc0 * (H1 * W1) + oy * W1 + ox0];
        #pragma unroll
        for (int o = 0; o < 7; o++) {
            out0[o]           = fmaxf(a0[o], 0.f);
            out0[H1 * W1 + o] = fmaxf(a1[o], 0.f);
        }
    }
}

// ---------------- conv1: 32->64, 23x35 -> 11x17 (dominant) ----------------
// block per image; 352 threads = 32 oc-pairs * 11 oy rows; 17-wide output rows in regs
__global__ void __launch_bounds__(352) k_conv1(const float* __restrict__ w1,
                                               const float* __restrict__ b1) {
    extern __shared__ float sm1[];
    float* sin = sm1;               // 25760
    float* sw  = sm1 + C0OUT;       // 18432
    int img = blockIdx.x, tid = threadIdx.x;
    const float* src = &g_c0[(size_t)img * C0OUT];
    for (int i = tid; i < C0OUT; i += 352) sin[i] = src[i];
    for (int i = tid; i < 64 * 32 * 9; i += 352) sw[i] = w1[i];
    __syncthreads();
    int oc0 = (tid / 11) * 2;
    int oy  = tid % 11;
    float a0[17], a1[17];
    float bb0 = __ldg(&b1[oc0]), bb1 = __ldg(&b1[oc0 + 1]);
    #pragma unroll
    for (int o = 0; o < 17; o++) { a0[o] = bb0; a1[o] = bb1; }
    for (int ic = 0; ic < 32; ic++) {
        float wr0[9], wr1[9];
        const float* wp0 = &sw[(oc0 * 32 + ic) * 9];
        const float* wp1 = &sw[((oc0 + 1) * 32 + ic) * 9];
        #pragma unroll
        for (int j = 0; j < 9; j++) { wr0[j] = wp0[j]; wr1[j] = wp1[j]; }
        #pragma unroll
        for (int ky = 0; ky < 3; ky++) {
            const float* row = &sin[ic * (H1 * W1) + (2 * oy + ky) * W1];
            float r[35];
            #pragma unroll
            for (int j = 0; j < 35; j++) r[j] = row[j];
            #pragma unroll
            for (int kx = 0; kx < 3; kx++) {
                float wa = wr0[ky * 3 + kx], wb = wr1[ky * 3 + kx];
                #pragma unroll
                for (int o = 0; o < 17; o++) {
                    a0[o] = fmaf(wa, r[2 * o + kx], a0[o]);
                    a1[o] = fmaf(wb, r[2 * o + kx], a1[o]);
                }
            }
        }
    }
    float* out = &g_c1[(size_t)img * C1OUT + oc0 * (H2 * W2) + oy * W2];
    #pragma unroll
    for (int o = 0; o < 17; o++) {
        out[o]           = fmaxf(a0[o], 0.f);
        out[H2 * W2 + o] = fmaxf(a1[o], 0.f);
    }
}

// ---------------- conv2: 64->32, 11x17 -> 5x8 ; writes x (+ rel_pos) ----------------
// block per image; 160 threads = 16 oc-pairs * 5 oy * 2 ox-groups(4 wide)
__global__ void __launch_bounds__(160) k_conv2(const float* __restrict__ w2,
                                               const float* __restrict__ b2,
                                               const float* __restrict__ relpos) {
    __shared__ float sin[64 * H2 * W2];  // 11968 floats = 47872B
    int img = blockIdx.x, tid = threadIdx.x;
    const float* src = &g_c1[(size_t)img * C1OUT];
    for (int i = tid; i < C1OUT; i += 160) sin[i] = src[i];
    __syncthreads();
    int ocg = tid / 10;
    int rem = tid % 10;
    int oy  = rem / 2;
    int ox0 = (rem % 2) * 4;
    int oc0 = ocg * 2;
    float acc[2][4];
    #pragma unroll
    for (int c = 0; c < 2; c++) {
        float bb = __ldg(&b2[oc0 + c]);
        #pragma unroll
        for (int o = 0; o < 4; o++) acc[c][o] = bb;
    }
    for (int ic = 0; ic < 64; ic++) {
        float wr[2][9];
        #pragma unroll
        for (int c = 0; c < 2; c++)
            #pragma unroll
            for (int j = 0; j < 9; j++)
                wr[c][j] = __ldg(&w2[((size_t)(oc0 + c) * 64 + ic) * 9 + j]);
        #pragma unroll
        for (int ky = 0; ky < 3; ky++) {
            const float* row = &sin[ic * (H2 * W2) + (2 * oy + ky) * W2 + 2 * ox0];
            float r[9];
            #pragma unroll
            for (int j = 0; j < 9; j++) r[j] = row[j];
            #pragma unroll
            for (int kx = 0; kx < 3; kx++) {
                #pragma unroll
                for (int o = 0; o < 4; o++) {
                    acc[0][o] = fmaf(wr[0][ky * 3 + kx], r[2 * o + kx], acc[0][o]);
                    acc[1][o] = fmaf(wr[1][ky * 3 + kx], r[2 * o + kx], acc[1][o]);
                }
            }
        }
    }
    float* out = &g_x[(size_t)img * SENS];
    #pragma unroll
    for (int c = 0; c < 2; c++)
        #pragma unroll
        for (int o = 0; o < 4; o++)
            out[(oc0 + c) * (H3 * W3) + oy * W3 + ox0 + o] = fmaxf(acc[c][o], 0.f);
    if (tid < 3) out[1280 + tid] = relpos[(size_t)img * 3 + tid];
}

// ---------------- sensory synapse precompute ----------------
// block = 4 images * 48 units = 192 threads; params chunked through smem
#define SCHUNK 128
__global__ void __launch_bounds__(192) k_sens() {
    extern __shared__ float sm2[];
    float4* sp = (float4*)sm2;                 // SCHUNK*48 float4 = 98304B
    float*  xs = sm2 + SCHUNK * UNITS * 4;     // 4*1283 floats
    int tid = threadIdx.x;
    int img0 = blockIdx.x * 4;
    for (int i = tid; i < 4 * SENS; i += 192) xs[i] = g_x[(size_t)img0 * SENS + i];
    int u = tid % UNITS, t = tid / UNITS;
    float accn = 0.f, accd = 0.f;
    for (int k0 = 0; k0 < SENS; k0 += SCHUNK) {
        int C = min(SCHUNK, SENS - k0);
        __syncthreads();
        for (int i = tid; i < C * UNITS; i += 192) sp[i] = g_sp[k0 * UNITS + i];
        __syncthreads();
        #pragma unroll 4
        for (int kk = 0; kk < C; kk++) {
            float4 p = sp[kk * UNITS + u];
            float xv = xs[t * SENS + k0 + kk];
            float nz = fmaf(xv, p.x, p.y);
            float e  = ex2f(nz);
            float s  = rcpf(1.f + e);
            accn = fmaf(p.z, s, accn);
            accd = fmaf(p.w, s, accd);
        }
    }
    g_sn[(size_t)(img0 + t) * UNITS + u] = accn;
    g_sd[(size_t)(img0 + t) * UNITS + u] = accd;
}

// ---------------- LTC recurrence + pooling + head ----------------
// one block per batch element; 288 threads = 48 post-units * 6 pre-groups(8)
__global__ void __launch_bounds__(288) k_ltc(const float* __restrict__ gleak,
                                             const float* __restrict__ vleak,
                                             const float* __restrict__ cm,
                                             const float* __restrict__ wout,
                                             const float* __restrict__ bout,
                                             const float* __restrict__ whead,
                                             const float* __restrict__ bhead,
                                             float* __restrict__ out) {
    extern __shared__ float sm3[];
    float4* rp   = (float4*)sm3;            // 2304 float4 = 9216 floats
    float*  sn   = sm3 + 9216;              // 2304
    float*  sd   = sn + 2304;               // 2304
    float*  v    = sd + 2304;               // 48
    float*  redn = v + 48;                  // 288
    float*  redd = redn + 288;              // 288
    float*  cmt  = redd + 288;              // 48
    float*  gl   = cmt + 48;                // 48
    float*  glvl = gl + 48;                 // 48
    float*  outsum = glvl + 48;             // 4
    int b = blockIdx.x, tid = threadIdx.x;
    for (int i = tid; i < UNITS * UNITS; i += 288) rp[i] = g_rp[i];
    for (int i = tid; i < NS * UNITS; i += 288) {
        sn[i] = g_sn[(size_t)b * NS * UNITS + i];
        sd[i] = g_sd[(size_t)b * NS * UNITS + i];
    }
    if (tid < UNITS) {
        v[tid] = 0.f;
        cmt[tid] = cm[tid] * 6.f;
        gl[tid]  = gleak[tid];
        glvl[tid] = gleak[tid] * vleak[tid];
    }
    if (tid < 4) outsum[tid] = 0.f;
    __syncthreads();
    int u = tid % UNITS, g = tid / UNITS;
    for (int s = 0; s < NS; s++) {
        for (int it = 0; it < 6; it++) {
            float accn = 0.f, accd = 0.f;
            #pragma unroll
            for (int j = 0; j < 8; j++) {
                int p = g * 8 + j;
                float4 q = rp[p * UNITS + u];
                float nz = fmaf(v[p], q.x, q.y);
                float e  = ex2f(nz);
                float sg = rcpf(1.f + e);
                accn = fmaf(q.z, sg, accn);
                accd = fmaf(q.w, sg, accd);
            }
            redn[g * UNITS + u] = accn;
            redd[g * UNITS + u] = accd;
            __syncthreads();
            if (tid < UNITS) {
                float a = 0.f, d = 0.f;
                #pragma unroll
                for (int gg = 0; gg < 6; gg++) { a += redn[gg * UNITS + tid]; d += redd[gg * UNITS + tid]; }
                float vv  = v[tid];
                float num = fmaf(cmt[tid], vv, glvl[tid]) + a + sn[s * UNITS + tid];
                float den = cmt[tid] + gl[tid] + d + sd[s * UNITS + tid] + 1e-8f;
                v[tid] = num * rcpf(den);
            }
            __syncthreads();
        }
        if (tid < 4) outsum[tid] += v[tid];
    }
    __syncthreads();
    if (tid == 0) {
        float p[4];
        #pragma unroll
        for (int m = 0; m < 4; m++)
            p[m] = outsum[m] * (1.f / 48.f) * wout[m] + bout[m];
        #pragma unroll
        for (int j = 0; j < 2; j++) {
            float h = bhead[j];
            #pragma unroll
            for (int m = 0; m < 4; m++) h = fmaf(p[m], whead[m * 2 + j], h);
            out[b * 2 + j] = tanhf(h);
        }
    }
}

// ---------------- launch ----------------
extern "C" void kernel_launch(void* const* d_in, const int* in_sizes, int n_in,
                              void* d_out, int out_size) {
    const float* image   = (const float*)d_in[0];
    const float* rel_pos = (const float*)d_in[1];
    const float* w0 = (const float*)d_in[2];
    const float* b0 = (const float*)d_in[3];
    const float* w1 = (const float*)d_in[4];
    const float* b1 = (const float*)d_in[5];
    const float* w2 = (const float*)d_in[6];
    const float* b2 = (const float*)d_in[7];
    const float* input_w = (const float*)d_in[8];
    const float* input_b = (const float*)d_in[9];
    const float* gleak = (const float*)d_in[10];
    const float* vleak = (const float*)d_in[11];
    const float* cm    = (const float*)d_in[12];
    const float* sigma = (const float*)d_in[13];
    const float* mu    = (const float*)d_in[14];
    const float* w_syn = (const float*)d_in[15];
    const float* erev  = (const float*)d_in[16];
    const float* s_sigma = (const float*)d_in[17];
    const float* s_mu    = (const float*)d_in[18];
    const float* s_w     = (const float*)d_in[19];
    const float* s_erev  = (const float*)d_in[20];
    const float* w_out = (const float*)d_in[21];
    const float* b_out = (const float*)d_in[22];
    const float* w_head = (const float*)d_in[23];
    const float* b_head = (const float*)d_in[24];
    const int* syn_mask  = (const int*)d_in[25];
    const int* sens_mask = (const int*)d_in[26];
    float* out = (float*)d_out;

    // opt-in smem sizes (idempotent; safe every call)
    const int SM_CONV1 = (C0OUT + 64 * 32 * 9) * 4;                 // 176768
    const int SM_SENS  = SCHUNK * UNITS * 16 + 4 * SENS * 4;        // 118832
    const int SM_LTC   = (9216 + 2304 + 2304 + 48 + 288 + 288 + 48 + 48 + 48 + 4) * 4;
    cudaFuncSetAttribute(k_conv1, cudaFuncAttributeMaxDynamicSharedMemorySize, SM_CONV1);
    cudaFuncSetAttribute(k_sens,  cudaFuncAttributeMaxDynamicSharedMemorySize, SM_SENS);
    cudaFuncSetAttribute(k_ltc,   cudaFuncAttributeMaxDynamicSharedMemorySize, SM_LTC);

    k_prep_sens<<<(SENS * UNITS + 255) / 256, 256>>>(input_w, input_b, s_sigma, s_mu,
                                                     s_w, s_erev, sens_mask);
    k_prep_rec<<<(UNITS * UNITS + 255) / 256, 256>>>(sigma, mu, w_syn, erev, syn_mask);
    k_conv0<<<NIMG, 256>>>(image, w0, b0);
    k_conv1<<<NIMG, 352, SM_CONV1>>>(w1, b1);
    k_conv2<<<NIMG, 160>>>(w2, b2, rel_pos);
    k_sens<<<NIMG / 4, 192, SM_SENS>>>();
    k_ltc<<<NB, 288, SM_LTC>>>(gleak, vleak, cm, w_out, b_out, w_head, b_head, out);
}